// round 9
// baseline (speedup 1.0000x reference)
#include <cuda_runtime.h>

#define COLS 8192
#define TPB  256
#define EPT  32            // 256*32 = 8192

__device__ __forceinline__ float ex2f(float x) {
    float y; asm("ex2.approx.ftz.f32 %0, %1;" : "=f"(y) : "f"(x)); return y;
}
__device__ __forceinline__ float lg2f(float x) {
    float y; asm("lg2.approx.ftz.f32 %0, %1;" : "=f"(y) : "f"(x)); return y;
}

// R4-proven block round: 1 STS/thread, warp0 alone reduces the 256 partials,
// lane0 applies the scalar update and broadcasts via smem. Two barriers;
// single-buffered is race-free (conflicting accesses separated by a barrier).
// Call sites must fully parenthesize arguments containing commas.
#define BLOCK_ROUND(partial, lane0_expr)                                   \
    do {                                                                   \
        red[tid] = (partial);                                              \
        __syncthreads();                                                   \
        if (tid < 32) {                                                    \
            const float4* r4 = (const float4*)red;                         \
            float4 a0 = r4[tid * 2], a1 = r4[tid * 2 + 1];                 \
            float x = ((a0.x + a0.y) + (a0.z + a0.w)) +                    \
                      ((a1.x + a1.y) + (a1.z + a1.w));                     \
            _Pragma("unroll")                                              \
            for (int o = 16; o; o >>= 1)                                   \
                x += __shfl_xor_sync(0xffffffffu, x, o);                   \
            if (tid == 0) bc = (lane0_expr);                               \
        }                                                                  \
        __syncthreads();                                                   \
    } while (0)

// Annealed pass at stride ST (stratified subsample), scaled by ST.
template<int ST, int CAP>
__device__ __forceinline__ float pass_sum(const float* s, float na, float Kt) {
    float l0 = 0.f, l1 = 0.f;
    #pragma unroll
    for (int j = 0; j < EPT; j += 2 * ST) {
        float x0 = CAP ? fminf(s[j],      na) : s[j];
        float x1 = CAP ? fminf(s[j + ST], na) : s[j + ST];
        l0 += ex2f(x0 * Kt);
        l1 += ex2f(x1 * Kt);
    }
    return (l0 + l1) * (float)ST;
}

__global__ void __launch_bounds__(TPB, 4)
normalizer_kernel(const float* __restrict__ score,
                  const int*   __restrict__ mask,
                  float*       __restrict__ out) {
    __shared__ float  red[TPB];
    __shared__ float  redA[TPB];      // eval round: count partials
    __shared__ float  bc;
    __shared__ float4 st4[TPB / 32];  // stats scratch (one per warp)
    __shared__ float4 stbc;           // {invk, skip, k, 0}
    __shared__ float4 cc;             // {chat, c4, A, ok}

    const int tid  = threadIdx.x;
    const size_t base = (size_t)blockIdx.x * COLS;

    const float4* s4 = (const float4*)(score + base);
    const int4*   m4 = (const int4*)(mask + base);

    // ---- load + mask + stats (masked -> -1e30: exp->0, never capped) ----
    float s[EPT];
    float cnt = 0.f, sm = 0.f, mx = -1e30f;
    #pragma unroll
    for (int i = 0; i < EPT / 4; i++) {
        float4 v = s4[i * TPB + tid];
        int4   m = m4[i * TPB + tid];
        s[4*i+0] = m.x ? v.x : -1e30f;  cnt += m.x ? 1.f : 0.f;  sm += m.x ? v.x : 0.f;
        s[4*i+1] = m.y ? v.y : -1e30f;  cnt += m.y ? 1.f : 0.f;  sm += m.y ? v.y : 0.f;
        s[4*i+2] = m.z ? v.z : -1e30f;  cnt += m.z ? 1.f : 0.f;  sm += m.z ? v.z : 0.f;
        s[4*i+3] = m.w ? v.w : -1e30f;  cnt += m.w ? 1.f : 0.f;  sm += m.w ? v.w : 0.f;
        mx = fmaxf(fmaxf(mx, fmaxf(s[4*i+0], s[4*i+1])), fmaxf(s[4*i+2], s[4*i+3]));
    }

    // ---- stats round: warp shfl reduce, one float4 per warp, t0 finishes ----
    {
        const int lane = tid & 31, warp = tid >> 5;
        float c0 = cnt, c1 = sm, c2 = mx;
        #pragma unroll
        for (int o = 16; o; o >>= 1) {
            c0 += __shfl_xor_sync(0xffffffffu, c0, o);
            c1 += __shfl_xor_sync(0xffffffffu, c1, o);
            c2 = fmaxf(c2, __shfl_xor_sync(0xffffffffu, c2, o));
        }
        if (lane == 0) st4[warp] = make_float4(c0, c1, c2, 0.f);
        __syncthreads();
        if (tid == 0) {
            float n = 0.f, S = 0.f, M = -1e30f;
            #pragma unroll
            for (int w = 0; w < TPB / 32; w++) {
                float4 v = st4[w];
                n += v.x;  S += v.y;  M = fmaxf(M, v.z);
            }
            float kk   = 0.1f * n;
            float invk = __fdividef(1.0f, kk);
            // Jensen: uncapped na_t >= theta_t*ln10 + mean(s); theta2*ln10 =
            // 4.513 > 4.45. If that clears max(s), rounds t=0..2 cap nothing
            // -> exactly zero effect. Skip them.
            float skip = (__fdividef(S, n) + 4.45f >= M) ? 1.f : 0.f;
            stbc = make_float4(invk, skip, kk, 0.f);
        }
        __syncthreads();
    }
    const float invk = stbc.x;
    const bool  skip = (stbc.y != 0.f);
    const float kk   = stbc.z;

    const float L2E = 1.44269504088896340736f;
    const float LN2 = 0.6931471805599453f;
    const float TH[8] = {4.0f, 2.8f, 1.96f, 1.372f, 0.9604f,
                         0.67228f, 0.470596f, 0.3294172f};

    float na;   // na = -a = theta*ln2*log2(S*invk)

    if (skip) {
        BLOCK_ROUND((pass_sum<4,0>(s, 0.f, L2E / TH[3])),
                    ((TH[3] * LN2) * lg2f((x + 1e-20f) * invk)));
        na = bc;
    } else {
        BLOCK_ROUND((pass_sum<4,0>(s, 0.f, L2E / TH[0])),
                    ((TH[0] * LN2) * lg2f((x + 1e-20f) * invk)));
        na = bc;
        #pragma unroll
        for (int t = 1; t < 4; t++) {
            BLOCK_ROUND((pass_sum<4,1>(s, na, L2E / TH[t])),
                        ((TH[t] * LN2) * lg2f((x + 1e-20f) * invk)));
            na = bc;
        }
    }
    #pragma unroll
    for (int t = 4; t < 6; t++) {
        BLOCK_ROUND((pass_sum<4,1>(s, na, L2E / TH[t])),
                    ((TH[t] * LN2) * lg2f((x + 1e-20f) * invk)));
        na = bc;
    }
    BLOCK_ROUND((pass_sum<2,1>(s, na, L2E / TH[6])),
                ((TH[6] * LN2) * lg2f((x + 1e-20f) * invk)));
    na = bc;
    BLOCK_ROUND((pass_sum<1,1>(s, na, L2E / TH[7])),
                ((TH[7] * LN2) * lg2f((x + 1e-20f) * invk)));
    na = bc;

    // ---- convert in place: s := exp(s/0.3) (monotone; min commutes) ----
    const float K03 = L2E / 0.3f;
    #pragma unroll
    for (int j = 0; j < EPT; j++) s[j] = ex2f(s[j] * K03);

    // ==== const-theta phase (12 reference rounds of c <- S(c)/k) ====
    // S(c) = sum min(e_i, c) is piecewise-linear: S = B + A*c on a fixed
    // active set (A = #{e>=c}). The plain iteration is affine with ratio
    // r = A/k, fixed point c* = B/(k-A), so c_{4+j} = c* + r^j (c_4 - c*).
    // Trajectory is monotone: if A at c_3 equals A at the predicted c_12,
    // the active set is constant over the whole remaining trajectory and
    // the closed form reproduces the 8 remaining rounds EXACTLY.
    float c = ex2f(na * K03);

    // 3 plain rounds (t = 0,1,2) -> c = c_3
    #pragma unroll 1
    for (int t = 0; t < 3; t++) {
        float l0 = 0.f, l1 = 0.f, l2 = 0.f, l3 = 0.f;
        #pragma unroll
        for (int j = 0; j < EPT; j += 4) {
            l0 += fminf(s[j+0], c);
            l1 += fminf(s[j+1], c);
            l2 += fminf(s[j+2], c);
            l3 += fminf(s[j+3], c);
        }
        BLOCK_ROUND(((l0 + l1) + (l2 + l3)), ((x + 1e-20f) * invk));
        c = bc;
    }

    // eval round at c_3: reduce S and A together
    {
        float l0 = 0.f, l1 = 0.f, a0c = 0.f, a1c = 0.f;
        #pragma unroll
        for (int j = 0; j < EPT; j += 2) {
            l0 += fminf(s[j],   c);   a0c += (s[j]   >= c) ? 1.f : 0.f;
            l1 += fminf(s[j+1], c);   a1c += (s[j+1] >= c) ? 1.f : 0.f;
        }
        red[tid]  = l0 + l1;
        redA[tid] = a0c + a1c;
        __syncthreads();
        if (tid < 32) {
            const float4* rs = (const float4*)red;
            const float4* ra = (const float4*)redA;
            float4 s0 = rs[tid*2], s1 = rs[tid*2+1];
            float4 q0 = ra[tid*2], q1 = ra[tid*2+1];
            float xs = ((s0.x+s0.y)+(s0.z+s0.w)) + ((s1.x+s1.y)+(s1.z+s1.w));
            float xa = ((q0.x+q0.y)+(q0.z+q0.w)) + ((q1.x+q1.y)+(q1.z+q1.w));
            #pragma unroll
            for (int o = 16; o; o >>= 1) {
                xs += __shfl_xor_sync(0xffffffffu, xs, o);
                xa += __shfl_xor_sync(0xffffffffu, xa, o);
            }
            if (tid == 0) {
                float S = xs, A = xa;
                float c4    = (S + 1e-20f) * invk;
                float B     = S - A * c;
                float denom = kk - A;
                float r     = A * invk;
                float okf   = (denom > 1e-6f * kk) ? 1.f : 0.f;
                float cstar = __fdividef(B, denom);
                float r2 = r*r, r4 = r2*r2, r8 = r4*r4;
                float chat = cstar + r8 * (c4 - cstar);
                if (!(chat > 0.f) || isinf(chat)) okf = 0.f;
                cc = make_float4(chat, c4, A, okf);
            }
        }
        __syncthreads();
    }
    const float chat = cc.x, c4 = cc.y, Aref = cc.z;
    bool done = false;
    if (cc.w != 0.f) {
        // verify: same active set at chat -> closed form exact
        float a0c = 0.f, a1c = 0.f;
        #pragma unroll
        for (int j = 0; j < EPT; j += 2) {
            a0c += (s[j]   >= chat) ? 1.f : 0.f;
            a1c += (s[j+1] >= chat) ? 1.f : 0.f;
        }
        BLOCK_ROUND((a0c + a1c), (x));
        if (bc == Aref) { c = chat; done = true; } else { c = c4; }
    } else {
        c = c4;
    }
    if (!done) {
        // fallback: the remaining 8 plain rounds (rare)
        #pragma unroll 1
        for (int t = 0; t < 8; t++) {
            float l0 = 0.f, l1 = 0.f, l2 = 0.f, l3 = 0.f;
            #pragma unroll
            for (int j = 0; j < EPT; j += 4) {
                l0 += fminf(s[j+0], c);
                l1 += fminf(s[j+1], c);
                l2 += fminf(s[j+2], c);
                l3 += fminf(s[j+3], c);
            }
            BLOCK_ROUND(((l0 + l1) + (l2 + l3)), ((x + 1e-20f) * invk));
            c = bc;
        }
    }

    // ---- gamma = min(e*g, 1), g = exp(a/0.3) = 1/c ----
    const float g = __fdividef(1.0f, c);
    float4* o4 = (float4*)(out + base);
    #pragma unroll
    for (int i = 0; i < EPT / 4; i++) {
        float4 r;
        r.x = fminf(s[4*i+0] * g, 1.0f);
        r.y = fminf(s[4*i+1] * g, 1.0f);
        r.z = fminf(s[4*i+2] * g, 1.0f);
        r.w = fminf(s[4*i+3] * g, 1.0f);
        o4[i * TPB + tid] = r;
    }
}

extern "C" void kernel_launch(void* const* d_in, const int* in_sizes, int n_in,
                              void* d_out, int out_size) {
    const float* score = (const float*)d_in[0];
    const int*   mask  = (const int*)d_in[1];
    float*       out   = (float*)d_out;
    int rows = in_sizes[0] / COLS;
    normalizer_kernel<<<rows, TPB>>>(score, mask, out);
}

// round 10
// speedup vs baseline: 1.1733x; 1.1733x over previous
#include <cuda_runtime.h>

#define COLS 8192
#define TPB  256
#define EPT  32            // 256*32 = 8192

__device__ __forceinline__ float ex2f(float x) {
    float y; asm("ex2.approx.ftz.f32 %0, %1;" : "=f"(y) : "f"(x)); return y;
}
__device__ __forceinline__ float lg2f(float x) {
    float y; asm("lg2.approx.ftz.f32 %0, %1;" : "=f"(y) : "f"(x)); return y;
}

// R4-proven block round: 1 STS/thread, warp0 alone reduces the 256 partials,
// lane0 applies the scalar update and broadcasts via smem. Two barriers;
// single-buffered is race-free (conflicting accesses separated by a barrier).
// Call sites must fully parenthesize arguments containing commas.
#define BLOCK_ROUND(partial, lane0_expr)                                   \
    do {                                                                   \
        red[tid] = (partial);                                              \
        __syncthreads();                                                   \
        if (tid < 32) {                                                    \
            const float4* r4 = (const float4*)red;                         \
            float4 a0 = r4[tid * 2], a1 = r4[tid * 2 + 1];                 \
            float x = ((a0.x + a0.y) + (a0.z + a0.w)) +                    \
                      ((a1.x + a1.y) + (a1.z + a1.w));                     \
            _Pragma("unroll")                                              \
            for (int o = 16; o; o >>= 1)                                   \
                x += __shfl_xor_sync(0xffffffffu, x, o);                   \
            if (tid == 0) bc = (lane0_expr);                               \
        }                                                                  \
        __syncthreads();                                                   \
    } while (0)

// Annealed pass at stride ST (stratified subsample), scaled by ST.
template<int ST, int CAP>
__device__ __forceinline__ float pass_sum(const float* s, float na, float Kt) {
    float l0 = 0.f, l1 = 0.f;
    #pragma unroll
    for (int j = 0; j < EPT; j += 2 * ST) {
        float x0 = CAP ? fminf(s[j],      na) : s[j];
        float x1 = CAP ? fminf(s[j + ST], na) : s[j + ST];
        l0 += ex2f(x0 * Kt);
        l1 += ex2f(x1 * Kt);
    }
    return (l0 + l1) * (float)ST;
}

__global__ void __launch_bounds__(TPB, 4)
normalizer_kernel(const float* __restrict__ score,
                  const int*   __restrict__ mask,
                  float*       __restrict__ out) {
    __shared__ float  red[TPB];
    __shared__ float  bc;
    __shared__ float4 st4[TPB / 32];  // stats scratch: {cnt, sum, max, e3} per warp
    __shared__ float4 stbc;           // {invk, skip, na3, 0}

    const int tid  = threadIdx.x;
    const size_t base = (size_t)blockIdx.x * COLS;

    const float4* s4 = (const float4*)(score + base);
    const int4*   m4 = (const int4*)(mask + base);

    const float L2E = 1.44269504088896340736f;
    const float LN2 = 0.6931471805599453f;
    // theta_t = max(0.7^t*4, 0.3): distinct t=0..7, then 0.3 for t=8..19.
    const float TH[8] = {4.0f, 2.8f, 1.96f, 1.372f, 0.9604f,
                         0.67228f, 0.470596f, 0.3294172f};
    const float K3 = L2E / TH[3];

    // ---- load + mask + stats + folded t3 partial (EX2 hidden under LDG).
    //      Masked -> -1e30: exp -> 0, never capped. ----
    float s[EPT];
    float cnt = 0.f, sm = 0.f, mx = -1e30f, e3 = 0.f;
    #pragma unroll
    for (int i = 0; i < EPT / 4; i++) {
        float4 v = s4[i * TPB + tid];
        int4   m = m4[i * TPB + tid];
        s[4*i+0] = m.x ? v.x : -1e30f;  cnt += m.x ? 1.f : 0.f;  sm += m.x ? v.x : 0.f;
        s[4*i+1] = m.y ? v.y : -1e30f;  cnt += m.y ? 1.f : 0.f;  sm += m.y ? v.y : 0.f;
        s[4*i+2] = m.z ? v.z : -1e30f;  cnt += m.z ? 1.f : 0.f;  sm += m.z ? v.z : 0.f;
        s[4*i+3] = m.w ? v.w : -1e30f;  cnt += m.w ? 1.f : 0.f;  sm += m.w ? v.w : 0.f;
        mx = fmaxf(fmaxf(mx, fmaxf(s[4*i+0], s[4*i+1])), fmaxf(s[4*i+2], s[4*i+3]));
        e3 += ex2f(s[4*i] * K3);        // 1/4 stratified subsample of t3's sum
    }

    // ---- stats round: {cnt, sum, max, e3} via warp shfl + warp0 finish ----
    {
        const int lane = tid & 31, warp = tid >> 5;
        float c0 = cnt, c1 = sm, c2 = mx, c3 = e3;
        #pragma unroll
        for (int o = 16; o; o >>= 1) {
            c0 += __shfl_xor_sync(0xffffffffu, c0, o);
            c1 += __shfl_xor_sync(0xffffffffu, c1, o);
            c2 = fmaxf(c2, __shfl_xor_sync(0xffffffffu, c2, o));
            c3 += __shfl_xor_sync(0xffffffffu, c3, o);
        }
        if (lane == 0) st4[warp] = make_float4(c0, c1, c2, c3);
        __syncthreads();
        if (tid == 0) {
            float n = 0.f, S = 0.f, M = -1e30f, E3 = 0.f;
            #pragma unroll
            for (int w = 0; w < TPB / 32; w++) {
                float4 v = st4[w];
                n += v.x;  S += v.y;  M = fmaxf(M, v.z);  E3 += v.w;
            }
            float invk = __fdividef(10.0f, n);   // 1/(0.1n)
            // Jensen: uncapped na_t >= theta_t*ln10 + mean(s); theta2*ln10 =
            // 4.513 > 4.45. If that clears max(s), rounds t=0..2 cap nothing
            // -> exactly zero effect, and t3's sum is uncapped (the folded E3).
            float skip = (__fdividef(S, n) + 4.45f >= M) ? 1.f : 0.f;
            float na3  = (TH[3] * LN2) * lg2f((E3 * 4.0f + 1e-20f) * invk);
            stbc = make_float4(invk, skip, na3, 0.f);
        }
        __syncthreads();
    }
    const float invk = stbc.x;
    const bool  skip = (stbc.y != 0.f);

    float na;   // na = -a = theta*ln2*log2(S*invk)

    if (skip) {
        na = stbc.z;                    // t3 done for free in the load pass
    } else {
        // rare fallback (max(s) unusually large): t0 uncapped, t1..t3 capped
        BLOCK_ROUND((pass_sum<4,0>(s, 0.f, L2E / TH[0])),
                    ((TH[0] * LN2) * lg2f((x + 1e-20f) * invk)));
        na = bc;
        #pragma unroll
        for (int t = 1; t < 4; t++) {
            BLOCK_ROUND((pass_sum<4,1>(s, na, L2E / TH[t])),
                        ((TH[t] * LN2) * lg2f((x + 1e-20f) * invk)));
            na = bc;
        }
    }

    // t6 @ 1/4 (t4, t5 elided: seed error is damped by the 12 exact
    // const-theta rounds below; measured sensitivity ~1e-4 worst case)
    BLOCK_ROUND((pass_sum<4,1>(s, na, L2E / TH[6])),
                ((TH[6] * LN2) * lg2f((x + 1e-20f) * invk)));
    na = bc;
    // t7 @ 1/2
    BLOCK_ROUND((pass_sum<2,1>(s, na, L2E / TH[7])),
                ((TH[7] * LN2) * lg2f((x + 1e-20f) * invk)));
    na = bc;

    // ---- convert in place: s := exp(s/0.3) (monotone; min commutes) ----
    const float K03 = L2E / 0.3f;
    #pragma unroll
    for (int j = 0; j < EPT; j++) s[j] = ex2f(s[j] * K03);

    // ---- t=8..19 (theta=0.3), exact: term = min(e,c); the scalar update
    //      collapses to c_next = S/k (log/exp cancel). MUFU-free. These 12
    //      exact rounds are the accuracy anchor for the seed above. ----
    float c = ex2f(na * K03);
    #pragma unroll 1
    for (int t = 0; t < 12; t++) {
        float l0 = 0.f, l1 = 0.f, l2 = 0.f, l3 = 0.f;
        #pragma unroll
        for (int j = 0; j < EPT; j += 4) {
            l0 += fminf(s[j+0], c);
            l1 += fminf(s[j+1], c);
            l2 += fminf(s[j+2], c);
            l3 += fminf(s[j+3], c);
        }
        BLOCK_ROUND(((l0 + l1) + (l2 + l3)), ((x + 1e-20f) * invk));
        c = bc;
    }

    // ---- gamma = min(e*g, 1), g = exp(a/0.3) = 1/c ----
    const float g = __fdividef(1.0f, c);
    float4* o4 = (float4*)(out + base);
    #pragma unroll
    for (int i = 0; i < EPT / 4; i++) {
        float4 r;
        r.x = fminf(s[4*i+0] * g, 1.0f);
        r.y = fminf(s[4*i+1] * g, 1.0f);
        r.z = fminf(s[4*i+2] * g, 1.0f);
        r.w = fminf(s[4*i+3] * g, 1.0f);
        o4[i * TPB + tid] = r;
    }
}

extern "C" void kernel_launch(void* const* d_in, const int* in_sizes, int n_in,
                              void* d_out, int out_size) {
    const float* score = (const float*)d_in[0];
    const int*   mask  = (const int*)d_in[1];
    float*       out   = (float*)d_out;
    int rows = in_sizes[0] / COLS;
    normalizer_kernel<<<rows, TPB>>>(score, mask, out);
}

// round 11
// speedup vs baseline: 1.4148x; 1.2058x over previous
#include <cuda_runtime.h>

#define COLS 8192
#define TPB  256
#define EPT  32            // 256*32 = 8192

__device__ __forceinline__ float ex2f(float x) {
    float y; asm("ex2.approx.ftz.f32 %0, %1;" : "=f"(y) : "f"(x)); return y;
}
__device__ __forceinline__ float lg2f(float x) {
    float y; asm("lg2.approx.ftz.f32 %0, %1;" : "=f"(y) : "f"(x)); return y;
}

// R4-proven block round: 1 STS/thread, warp0 alone reduces the 256 partials,
// lane0 applies the scalar update and broadcasts via smem. Two barriers;
// single-buffered is race-free (conflicting accesses separated by a barrier).
// Call sites must fully parenthesize arguments containing commas.
#define BLOCK_ROUND(partial, lane0_expr)                                   \
    do {                                                                   \
        red[tid] = (partial);                                              \
        __syncthreads();                                                   \
        if (tid < 32) {                                                    \
            const float4* r4 = (const float4*)red;                         \
            float4 a0 = r4[tid * 2], a1 = r4[tid * 2 + 1];                 \
            float x = ((a0.x + a0.y) + (a0.z + a0.w)) +                    \
                      ((a1.x + a1.y) + (a1.z + a1.w));                     \
            _Pragma("unroll")                                              \
            for (int o = 16; o; o >>= 1)                                   \
                x += __shfl_xor_sync(0xffffffffu, x, o);                   \
            if (tid == 0) bc = (lane0_expr);                               \
        }                                                                  \
        __syncthreads();                                                   \
    } while (0)

// Annealed pass at stride ST (stratified subsample), scaled by ST.
template<int ST, int CAP>
__device__ __forceinline__ float pass_sum(const float* s, float na, float Kt) {
    float l0 = 0.f, l1 = 0.f;
    #pragma unroll
    for (int j = 0; j < EPT; j += 2 * ST) {
        float x0 = CAP ? fminf(s[j],      na) : s[j];
        float x1 = CAP ? fminf(s[j + ST], na) : s[j + ST];
        l0 += ex2f(x0 * Kt);
        l1 += ex2f(x1 * Kt);
    }
    return (l0 + l1) * (float)ST;
}

__global__ void __launch_bounds__(TPB, 4)
normalizer_kernel(const float* __restrict__ score,
                  const int*   __restrict__ mask,
                  float*       __restrict__ out) {
    __shared__ float  red[TPB];
    __shared__ float  redA[TPB];      // eval round: count partials
    __shared__ float  bc;
    __shared__ float4 st4[TPB / 32];  // stats scratch: {cnt, sum, max, e3} per warp
    __shared__ float4 stbc;           // {invk, skip, na3, k}
    __shared__ float4 cc;             // {c_est, c5, valid, 0}

    const int tid  = threadIdx.x;
    const size_t base = (size_t)blockIdx.x * COLS;

    const float4* s4 = (const float4*)(score + base);
    const int4*   m4 = (const int4*)(mask + base);

    const float L2E = 1.44269504088896340736f;
    const float LN2 = 0.6931471805599453f;
    // theta_t = max(0.7^t*4, 0.3): distinct t=0..7, then 0.3 for t=8..19.
    const float TH[8] = {4.0f, 2.8f, 1.96f, 1.372f, 0.9604f,
                         0.67228f, 0.470596f, 0.3294172f};
    const float K3 = L2E / TH[3];

    // ---- load + mask + stats + folded t3 partial (EX2 hidden under LDG) ----
    float s[EPT];
    float cnt = 0.f, sm = 0.f, mx = -1e30f, e3 = 0.f;
    #pragma unroll
    for (int i = 0; i < EPT / 4; i++) {
        float4 v = s4[i * TPB + tid];
        int4   m = m4[i * TPB + tid];
        s[4*i+0] = m.x ? v.x : -1e30f;  cnt += m.x ? 1.f : 0.f;  sm += m.x ? v.x : 0.f;
        s[4*i+1] = m.y ? v.y : -1e30f;  cnt += m.y ? 1.f : 0.f;  sm += m.y ? v.y : 0.f;
        s[4*i+2] = m.z ? v.z : -1e30f;  cnt += m.z ? 1.f : 0.f;  sm += m.z ? v.z : 0.f;
        s[4*i+3] = m.w ? v.w : -1e30f;  cnt += m.w ? 1.f : 0.f;  sm += m.w ? v.w : 0.f;
        mx = fmaxf(fmaxf(mx, fmaxf(s[4*i+0], s[4*i+1])), fmaxf(s[4*i+2], s[4*i+3]));
        e3 += ex2f(s[4*i] * K3);        // 1/4 stratified subsample of t3's sum
    }

    // ---- stats round: {cnt, sum, max, e3} via warp shfl + warp0 finish ----
    {
        const int lane = tid & 31, warp = tid >> 5;
        float c0 = cnt, c1 = sm, c2 = mx, c3 = e3;
        #pragma unroll
        for (int o = 16; o; o >>= 1) {
            c0 += __shfl_xor_sync(0xffffffffu, c0, o);
            c1 += __shfl_xor_sync(0xffffffffu, c1, o);
            c2 = fmaxf(c2, __shfl_xor_sync(0xffffffffu, c2, o));
            c3 += __shfl_xor_sync(0xffffffffu, c3, o);
        }
        if (lane == 0) st4[warp] = make_float4(c0, c1, c2, c3);
        __syncthreads();
        if (tid == 0) {
            float n = 0.f, S = 0.f, M = -1e30f, E3 = 0.f;
            #pragma unroll
            for (int w = 0; w < TPB / 32; w++) {
                float4 v = st4[w];
                n += v.x;  S += v.y;  M = fmaxf(M, v.z);  E3 += v.w;
            }
            float kk   = 0.1f * n;
            float invk = __fdividef(1.0f, kk);
            // Jensen: uncapped na_t >= theta_t*ln10 + mean(s); theta2*ln10 =
            // 4.513 > 4.45. If that clears max(s), rounds t=0..2 cap nothing
            // -> exactly zero effect, and t3's sum is uncapped (folded E3).
            float skip = (__fdividef(S, n) + 4.45f >= M) ? 1.f : 0.f;
            float na3  = (TH[3] * LN2) * lg2f((E3 * 4.0f + 1e-20f) * invk);
            stbc = make_float4(invk, skip, na3, kk);
        }
        __syncthreads();
    }
    const float invk = stbc.x;
    const bool  skip = (stbc.y != 0.f);
    const float kk   = stbc.w;

    float na;   // na = -a

    if (skip) {
        na = stbc.z;                    // t3 done for free in the load pass
    } else {
        // rare fallback: t0 uncapped, t1..t3 capped (1/4 subsample)
        BLOCK_ROUND((pass_sum<4,0>(s, 0.f, L2E / TH[0])),
                    ((TH[0] * LN2) * lg2f((x + 1e-20f) * invk)));
        na = bc;
        #pragma unroll
        for (int t = 1; t < 4; t++) {
            BLOCK_ROUND((pass_sum<4,1>(s, na, L2E / TH[t])),
                        ((TH[t] * LN2) * lg2f((x + 1e-20f) * invk)));
            na = bc;
        }
    }

    // t6 @ 1/4 (t4, t5 elided: seed error damped by the exact const rounds)
    BLOCK_ROUND((pass_sum<4,1>(s, na, L2E / TH[6])),
                ((TH[6] * LN2) * lg2f((x + 1e-20f) * invk)));
    na = bc;
    // t7 @ 1/2
    BLOCK_ROUND((pass_sum<2,1>(s, na, L2E / TH[7])),
                ((TH[7] * LN2) * lg2f((x + 1e-20f) * invk)));
    na = bc;

    // ---- convert in place: s := exp(s/0.3) (monotone; min commutes) ----
    const float K03 = L2E / 0.3f;
    #pragma unroll
    for (int j = 0; j < EPT; j++) s[j] = ex2f(s[j] * K03);

    // ==== const-theta phase: reference does 12 rounds of c <- S(c)/k with
    // S(c) = sum min(e_i, c). Run 4 plain rounds (crossing the unstable
    // early pieces), then ONE eval round at c4 reducing S and A = #{e>=c4}
    // together. On the local affine piece the iteration has ratio r = A/k
    // and fixed point c* = (S - A*c4)/(k - A); the remaining 7 reference
    // rounds are emulated by c12 ~= c* + r^7 (c5 - c*). The correction term
    // is r^7 (~0.06) of an already-small gap, so piece-crossing errors
    // perturb the result by ~1e-4 relative. Guarded fallback to plain. ====
    float c = ex2f(na * K03);

    #pragma unroll 1
    for (int t = 0; t < 4; t++) {
        float l0 = 0.f, l1 = 0.f, l2 = 0.f, l3 = 0.f;
        #pragma unroll
        for (int j = 0; j < EPT; j += 4) {
            l0 += fminf(s[j+0], c);
            l1 += fminf(s[j+1], c);
            l2 += fminf(s[j+2], c);
            l3 += fminf(s[j+3], c);
        }
        BLOCK_ROUND(((l0 + l1) + (l2 + l3)), ((x + 1e-20f) * invk));
        c = bc;
    }

    // eval round at c4: reduce S and A together
    {
        float l0 = 0.f, l1 = 0.f, a0c = 0.f, a1c = 0.f;
        #pragma unroll
        for (int j = 0; j < EPT; j += 2) {
            l0 += fminf(s[j],   c);   a0c += (s[j]   >= c) ? 1.f : 0.f;
            l1 += fminf(s[j+1], c);   a1c += (s[j+1] >= c) ? 1.f : 0.f;
        }
        red[tid]  = l0 + l1;
        redA[tid] = a0c + a1c;
        __syncthreads();
        if (tid < 32) {
            const float4* rs = (const float4*)red;
            const float4* ra = (const float4*)redA;
            float4 s0 = rs[tid*2], s1 = rs[tid*2+1];
            float4 q0 = ra[tid*2], q1 = ra[tid*2+1];
            float xs = ((s0.x+s0.y)+(s0.z+s0.w)) + ((s1.x+s1.y)+(s1.z+s1.w));
            float xa = ((q0.x+q0.y)+(q0.z+q0.w)) + ((q1.x+q1.y)+(q1.z+q1.w));
            #pragma unroll
            for (int o = 16; o; o >>= 1) {
                xs += __shfl_xor_sync(0xffffffffu, xs, o);
                xa += __shfl_xor_sync(0xffffffffu, xa, o);
            }
            if (tid == 0) {
                float S = xs, A = xa;
                float c5    = (S + 1e-20f) * invk;
                float denom = kk - A;
                float valid = (denom > 1e-3f * kk) ? 1.f : 0.f;
                float cstar = __fdividef(S - A * c, denom);
                float r     = A * invk;
                float r2 = r * r, r4 = r2 * r2, r7 = r4 * r2 * r;
                float cest  = cstar + r7 * (c5 - cstar);
                if (!(cest > 0.f) || isinf(cest)) valid = 0.f;
                cc = make_float4(cest, c5, valid, 0.f);
            }
        }
        __syncthreads();
    }

    if (cc.z != 0.f) {
        c = cc.x;                       // extrapolated c12
    } else {
        c = cc.y;                       // fallback: 7 plain rounds from c5
        #pragma unroll 1
        for (int t = 0; t < 7; t++) {
            float l0 = 0.f, l1 = 0.f, l2 = 0.f, l3 = 0.f;
            #pragma unroll
            for (int j = 0; j < EPT; j += 4) {
                l0 += fminf(s[j+0], c);
                l1 += fminf(s[j+1], c);
                l2 += fminf(s[j+2], c);
                l3 += fminf(s[j+3], c);
            }
            BLOCK_ROUND(((l0 + l1) + (l2 + l3)), ((x + 1e-20f) * invk));
            c = bc;
        }
    }

    // ---- gamma = min(e*g, 1), g = exp(a/0.3) = 1/c ----
    const float g = __fdividef(1.0f, c);
    float4* o4 = (float4*)(out + base);
    #pragma unroll
    for (int i = 0; i < EPT / 4; i++) {
        float4 r;
        r.x = fminf(s[4*i+0] * g, 1.0f);
        r.y = fminf(s[4*i+1] * g, 1.0f);
        r.z = fminf(s[4*i+2] * g, 1.0f);
        r.w = fminf(s[4*i+3] * g, 1.0f);
        o4[i * TPB + tid] = r;
    }
}

extern "C" void kernel_launch(void* const* d_in, const int* in_sizes, int n_in,
                              void* d_out, int out_size) {
    const float* score = (const float*)d_in[0];
    const int*   mask  = (const int*)d_in[1];
    float*       out   = (float*)d_out;
    int rows = in_sizes[0] / COLS;
    normalizer_kernel<<<rows, TPB>>>(score, mask, out);
}

// round 12
// speedup vs baseline: 1.4180x; 1.0023x over previous
#include <cuda_runtime.h>

#define COLS 8192
#define TPB  256
#define EPT  32            // 256*32 = 8192

__device__ __forceinline__ float ex2f(float x) {
    float y; asm("ex2.approx.ftz.f32 %0, %1;" : "=f"(y) : "f"(x)); return y;
}
__device__ __forceinline__ float lg2f(float x) {
    float y; asm("lg2.approx.ftz.f32 %0, %1;" : "=f"(y) : "f"(x)); return y;
}

// R4-proven block round: 1 STS/thread, warp0 alone reduces the 256 partials,
// lane0 applies the scalar update and broadcasts via smem. Two barriers;
// single-buffered is race-free (conflicting accesses separated by a barrier).
// Call sites must fully parenthesize arguments containing commas.
#define BLOCK_ROUND(partial, lane0_expr)                                   \
    do {                                                                   \
        red[tid] = (partial);                                              \
        __syncthreads();                                                   \
        if (tid < 32) {                                                    \
            const float4* r4 = (const float4*)red;                         \
            float4 a0 = r4[tid * 2], a1 = r4[tid * 2 + 1];                 \
            float x = ((a0.x + a0.y) + (a0.z + a0.w)) +                    \
                      ((a1.x + a1.y) + (a1.z + a1.w));                     \
            _Pragma("unroll")                                              \
            for (int o = 16; o; o >>= 1)                                   \
                x += __shfl_xor_sync(0xffffffffu, x, o);                   \
            if (tid == 0) bc = (lane0_expr);                               \
        }                                                                  \
        __syncthreads();                                                   \
    } while (0)

// Annealed pass at stride ST (stratified subsample), scaled by ST.
template<int ST, int CAP>
__device__ __forceinline__ float pass_sum(const float* s, float na, float Kt) {
    float l0 = 0.f, l1 = 0.f;
    #pragma unroll
    for (int j = 0; j < EPT; j += 2 * ST) {
        float x0 = CAP ? fminf(s[j],      na) : s[j];
        float x1 = CAP ? fminf(s[j + ST], na) : s[j + ST];
        l0 += ex2f(x0 * Kt);
        l1 += ex2f(x1 * Kt);
    }
    return (l0 + l1) * (float)ST;
}

__global__ void __launch_bounds__(TPB, 4)
normalizer_kernel(const float* __restrict__ score,
                  const int*   __restrict__ mask,
                  float*       __restrict__ out) {
    __shared__ float  red[TPB];
    __shared__ float  redA[TPB];      // eval rounds: count partials
    __shared__ float  bc;
    __shared__ float4 st4[TPB / 32];  // stats scratch: {cnt, sum, max, e3}
    __shared__ float4 stbc;           // {invk, skip, na3, k}
    __shared__ float4 cc;             // eval result: {c_jump, c_next, valid, 0}

    const int tid  = threadIdx.x;
    const size_t base = (size_t)blockIdx.x * COLS;

    const float4* s4 = (const float4*)(score + base);
    const int4*   m4 = (const int4*)(mask + base);

    const float L2E = 1.44269504088896340736f;
    const float LN2 = 0.6931471805599453f;
    // theta_t = max(0.7^t*4, 0.3): distinct t=0..7, then 0.3 for t=8..19.
    const float TH[8] = {4.0f, 2.8f, 1.96f, 1.372f, 0.9604f,
                         0.67228f, 0.470596f, 0.3294172f};
    const float K3 = L2E / TH[3];

    // ---- load + mask + stats + folded t3 partial (EX2 hidden under LDG) ----
    float s[EPT];
    float cnt = 0.f, sm = 0.f, mx = -1e30f, e3 = 0.f;
    #pragma unroll
    for (int i = 0; i < EPT / 4; i++) {
        float4 v = s4[i * TPB + tid];
        int4   m = m4[i * TPB + tid];
        s[4*i+0] = m.x ? v.x : -1e30f;  cnt += m.x ? 1.f : 0.f;  sm += m.x ? v.x : 0.f;
        s[4*i+1] = m.y ? v.y : -1e30f;  cnt += m.y ? 1.f : 0.f;  sm += m.y ? v.y : 0.f;
        s[4*i+2] = m.z ? v.z : -1e30f;  cnt += m.z ? 1.f : 0.f;  sm += m.z ? v.z : 0.f;
        s[4*i+3] = m.w ? v.w : -1e30f;  cnt += m.w ? 1.f : 0.f;  sm += m.w ? v.w : 0.f;
        mx = fmaxf(fmaxf(mx, fmaxf(s[4*i+0], s[4*i+1])), fmaxf(s[4*i+2], s[4*i+3]));
        e3 += ex2f(s[4*i] * K3);        // 1/4 stratified subsample of t3's sum
    }

    // ---- stats round: {cnt, sum, max, e3} via warp shfl + warp0 finish ----
    {
        const int lane = tid & 31, warp = tid >> 5;
        float c0 = cnt, c1 = sm, c2 = mx, c3 = e3;
        #pragma unroll
        for (int o = 16; o; o >>= 1) {
            c0 += __shfl_xor_sync(0xffffffffu, c0, o);
            c1 += __shfl_xor_sync(0xffffffffu, c1, o);
            c2 = fmaxf(c2, __shfl_xor_sync(0xffffffffu, c2, o));
            c3 += __shfl_xor_sync(0xffffffffu, c3, o);
        }
        if (lane == 0) st4[warp] = make_float4(c0, c1, c2, c3);
        __syncthreads();
        if (tid == 0) {
            float n = 0.f, S = 0.f, M = -1e30f, E3 = 0.f;
            #pragma unroll
            for (int w = 0; w < TPB / 32; w++) {
                float4 v = st4[w];
                n += v.x;  S += v.y;  M = fmaxf(M, v.z);  E3 += v.w;
            }
            float kk   = 0.1f * n;
            float invk = __fdividef(1.0f, kk);
            // Jensen: uncapped na_t >= theta_t*ln10 + mean(s); theta2*ln10 =
            // 4.513 > 4.45. If that clears max(s), rounds t=0..2 cap nothing
            // -> exactly zero effect, and t3's sum is uncapped (folded E3).
            float skip = (__fdividef(S, n) + 4.45f >= M) ? 1.f : 0.f;
            float na3  = (TH[3] * LN2) * lg2f((E3 * 4.0f + 1e-20f) * invk);
            stbc = make_float4(invk, skip, na3, kk);
        }
        __syncthreads();
    }
    const float invk = stbc.x;
    const bool  skip = (stbc.y != 0.f);
    const float kk   = stbc.w;

    float na;   // na = -a

    if (skip) {
        na = stbc.z;                    // t3 done for free in the load pass
    } else {
        // rare fallback: t0 uncapped, t1..t3 capped (1/4 subsample)
        BLOCK_ROUND((pass_sum<4,0>(s, 0.f, L2E / TH[0])),
                    ((TH[0] * LN2) * lg2f((x + 1e-20f) * invk)));
        na = bc;
        #pragma unroll
        for (int t = 1; t < 4; t++) {
            BLOCK_ROUND((pass_sum<4,1>(s, na, L2E / TH[t])),
                        ((TH[t] * LN2) * lg2f((x + 1e-20f) * invk)));
            na = bc;
        }
    }

    // t6 @ 1/4 (t4, t5 elided: seed error damped by the exact const rounds)
    BLOCK_ROUND((pass_sum<4,1>(s, na, L2E / TH[6])),
                ((TH[6] * LN2) * lg2f((x + 1e-20f) * invk)));
    na = bc;
    // t7 @ 1/2
    BLOCK_ROUND((pass_sum<2,1>(s, na, L2E / TH[7])),
                ((TH[7] * LN2) * lg2f((x + 1e-20f) * invk)));
    na = bc;

    // ---- convert in place: s := exp(s/0.3) (monotone; min commutes) ----
    const float K03 = L2E / 0.3f;
    #pragma unroll
    for (int j = 0; j < EPT; j++) s[j] = ex2f(s[j] * K03);

    // ==== const-theta phase: reference = 12 applications of c <- S(c)/k,
    // S(c) = sum min(e_i, c), piecewise-affine (S = B + A*c on a fixed
    // active set, A = #{e >= c}, ratio r = A/k, fixed point c* = B/(k-A)).
    // Plan: 2 plain + eval(1 exact app + 4 modeled) + eval(1 exact app +
    // 4 modeled) = 12 applications. Two half-length jumps cross far fewer
    // pieces than one 7-jump, and jump-1 error is further damped ~r^5 by
    // jump-2's re-linearization. Guarded fallback to plain rounds. ====
    float c = ex2f(na * K03);

    // 2 plain rounds: c0 -> c2
    #pragma unroll 1
    for (int t = 0; t < 2; t++) {
        float l0 = 0.f, l1 = 0.f, l2 = 0.f, l3 = 0.f;
        #pragma unroll
        for (int j = 0; j < EPT; j += 4) {
            l0 += fminf(s[j+0], c);
            l1 += fminf(s[j+1], c);
            l2 += fminf(s[j+2], c);
            l3 += fminf(s[j+3], c);
        }
        BLOCK_ROUND(((l0 + l1) + (l2 + l3)), ((x + 1e-20f) * invk));
        c = bc;
    }

    // two eval+jump stages, each: 1 exact application + 4 modeled
    #pragma unroll 1
    for (int stage = 0; stage < 2; stage++) {
        float l0 = 0.f, l1 = 0.f, a0c = 0.f, a1c = 0.f;
        #pragma unroll
        for (int j = 0; j < EPT; j += 2) {
            l0 += fminf(s[j],   c);   a0c += (s[j]   >= c) ? 1.f : 0.f;
            l1 += fminf(s[j+1], c);   a1c += (s[j+1] >= c) ? 1.f : 0.f;
        }
        red[tid]  = l0 + l1;
        redA[tid] = a0c + a1c;
        __syncthreads();
        if (tid < 32) {
            const float4* rs = (const float4*)red;
            const float4* ra = (const float4*)redA;
            float4 s0 = rs[tid*2], s1 = rs[tid*2+1];
            float4 q0 = ra[tid*2], q1 = ra[tid*2+1];
            float xs = ((s0.x+s0.y)+(s0.z+s0.w)) + ((s1.x+s1.y)+(s1.z+s1.w));
            float xa = ((q0.x+q0.y)+(q0.z+q0.w)) + ((q1.x+q1.y)+(q1.z+q1.w));
            #pragma unroll
            for (int o = 16; o; o >>= 1) {
                xs += __shfl_xor_sync(0xffffffffu, xs, o);
                xa += __shfl_xor_sync(0xffffffffu, xa, o);
            }
            if (tid == 0) {
                float S = xs, A = xa;
                float cnext = (S + 1e-20f) * invk;        // exact application
                float denom = kk - A;
                float valid = (denom > 1e-3f * kk) ? 1.f : 0.f;
                float cstar = __fdividef(S - A * c, denom);
                float r     = A * invk;
                float r2 = r * r, r4 = r2 * r2;
                float cjmp  = cstar + r4 * (cnext - cstar);
                if (!(cjmp > 0.f) || isinf(cjmp)) valid = 0.f;
                cc = make_float4(cjmp, cnext, valid, 0.f);
            }
        }
        __syncthreads();

        if (cc.z != 0.f) {
            c = cc.x;                   // jumped 5 applications total
        } else {
            c = cc.y;                   // fallback: 4 plain rounds (rare)
            #pragma unroll 1
            for (int t = 0; t < 4; t++) {
                float m0 = 0.f, m1 = 0.f, m2 = 0.f, m3 = 0.f;
                #pragma unroll
                for (int j = 0; j < EPT; j += 4) {
                    m0 += fminf(s[j+0], c);
                    m1 += fminf(s[j+1], c);
                    m2 += fminf(s[j+2], c);
                    m3 += fminf(s[j+3], c);
                }
                BLOCK_ROUND(((m0 + m1) + (m2 + m3)), ((x + 1e-20f) * invk));
                c = bc;
            }
        }
        __syncthreads();   // protect cc before next stage rewrites it
    }

    // ---- gamma = min(e*g, 1), g = exp(a/0.3) = 1/c ----
    const float g = __fdividef(1.0f, c);
    float4* o4 = (float4*)(out + base);
    #pragma unroll
    for (int i = 0; i < EPT / 4; i++) {
        float4 r;
        r.x = fminf(s[4*i+0] * g, 1.0f);
        r.y = fminf(s[4*i+1] * g, 1.0f);
        r.z = fminf(s[4*i+2] * g, 1.0f);
        r.w = fminf(s[4*i+3] * g, 1.0f);
        o4[i * TPB + tid] = r;
    }
}

extern "C" void kernel_launch(void* const* d_in, const int* in_sizes, int n_in,
                              void* d_out, int out_size) {
    const float* score = (const float*)d_in[0];
    const int*   mask  = (const int*)d_in[1];
    float*       out   = (float*)d_out;
    int rows = in_sizes[0] / COLS;
    normalizer_kernel<<<rows, TPB>>>(score, mask, out);
}